// round 15
// baseline (speedup 1.0000x reference)
#include <cuda_runtime.h>
#include <cuda_fp16.h>
#include <math.h>
#include <cstdint>

// Problem dims (fixed by dataset)
#define B_DIM 8192
#define I_DIM 1024
#define H_DIM 1024
#define N4    4096
#define K2    2048   // I+H
#define N_A   5120   // Wm(1024) + W_top(4096) fused N for GEMM_A
#define KDIM  1024   // K for both GEMMs

// ---------------- scratch (device globals; allocation-free) ----------------
__device__ __half g_axh [(size_t)B_DIM * K2];        // [fp16(x) | fp16(hx)]
__device__ __half g_bt  [(size_t)(N_A + N4) * KDIM]; // [Wm^T; W_top^T; W_bot^T]
__device__ __half g_c1p [(size_t)B_DIM * N4];        // x @ W_top  (P)
__device__ __half g_c2  [(size_t)B_DIM * N4];        // hx @ W_bot (Q)
__device__ float  g_part[(size_t)3 * B_DIM * 32];    // attn partials: dot, n1, imbm
__device__ float  g_hx2 [B_DIM];                     // sum hx^2 per row
__device__ float  g_hxbm[B_DIM];                     // sum bm*hx per row
__device__ float  g_bm2 [1];                         // ||bm||^2

__device__ __forceinline__ float sigmoidf_(float z) {
    return 1.0f / (1.0f + __expf(-z));
}
__device__ __forceinline__ float tanhf_(float z) {
    return 2.0f / (1.0f + __expf(-2.0f * z)) - 1.0f;
}
__device__ __forceinline__ uint32_t smem_u32(const void* p) {
    uint32_t a;
    asm("{ .reg .u64 t; cvta.to.shared.u64 t, %1; cvt.u32.u64 %0, t; }"
        : "=r"(a) : "l"(p));
    return a;
}
__device__ __forceinline__ uint32_t sw128(uint32_t off) {
    return off ^ ((off >> 3) & 0x70);
}
__device__ __forceinline__ uint32_t pack_half2(float a, float b) {
    __half2 h = __floats2half2_rn(a, b);
    return *reinterpret_cast<uint32_t*>(&h);
}

// ---------------------------------------------------------------------------
// Fused dual-GEMM (pinned engine) with attn-partial epilogue.
//   bid <  2560 : GEMM_A  x @ [Wm|W_top]^T   (N=5120)
//       nx <  8 : attn tile -> per-row partials only (no C store)
//       nx >= 8 : P tile    -> store g_c1p at col n0-1024
//   bid >= 2560 : GEMM_B  hx @ W_bot^T -> g_c2 at col n0
// ---------------------------------------------------------------------------
#define TM 128
#define TN 128
#define KC 64
#define A_STG 16384
#define B_STG 16384
#define STG   (A_STG + B_STG)          // 32KB per stage
#define NSTAGE 3
#define GEMM_SMEM (NSTAGE * STG)       // 96KB
#define GRID_A (( N_A / TN) * (B_DIM / TM))   // 40*64 = 2560
#define GRID_B (( N4  / TN) * (B_DIM / TM))   // 32*64 = 2048

__global__ __launch_bounds__(256, 2)
void hgemm_dual(const float* __restrict__ bm)
{
    extern __shared__ char smem_raw[];
    const uint32_t SM = smem_u32(smem_raw);

    const int tid  = threadIdx.x;
    const int wid  = tid >> 5;
    const int lane = tid & 31;
    const int wm   = (wid & 1) * 64;
    const int wn   = (wid >> 1) * 32;

    int bid = blockIdx.x;
    const __half* A;  const __half* BT;
    int m0, n0, is_attn = 0;
    __half* C = nullptr;  int Ncols = 0, cbase = 0;
    if (bid < GRID_A) {
        int nx = bid % (N_A / TN), my = bid / (N_A / TN);
        A = g_axh;
        BT = g_bt;
        m0 = my * TM;  n0 = nx * TN;
        if (nx < 8) { is_attn = 1; }
        else        { C = g_c1p; Ncols = N4; cbase = n0 - 1024; }
    } else {
        bid -= GRID_A;
        int nx = bid % (N4 / TN), my = bid / (N4 / TN);
        A = g_axh + 1024;
        BT = g_bt + (size_t)N_A * KDIM;
        m0 = my * TM;  n0 = nx * TN;
        C = g_c2;  Ncols = N4;  cbase = n0;        // FIX (was 0 in R14)
    }

    const int nc = KDIM / KC;      // 16

    auto load_chunk = [&](int c, int stage) {
        const int kk = c * KC;
        const __half* Ag = A  + (size_t)m0 * K2 + kk;
        const __half* Bg = BT + (size_t)n0 * KDIM + kk;
        const uint32_t sa = SM + stage * STG;
        const uint32_t sb = sa + A_STG;
#pragma unroll
        for (int t = 0; t < 4; t++) {
            int idx = tid + 256 * t;
            int rr = idx >> 3, ii = idx & 7;
            uint32_t off = sw128((uint32_t)(rr * 128 + ii * 16));
            asm volatile("cp.async.cg.shared.global [%0], [%1], 16;"
                         :: "r"(sa + off), "l"(Ag + (size_t)rr * K2 + ii * 8));
            asm volatile("cp.async.cg.shared.global [%0], [%1], 16;"
                         :: "r"(sb + off), "l"(Bg + (size_t)rr * KDIM + ii * 8));
        }
        asm volatile("cp.async.commit_group;" ::: "memory");
    };

    float acc[4][4][4];
#pragma unroll
    for (int mi = 0; mi < 4; mi++)
#pragma unroll
        for (int ni = 0; ni < 4; ni++)
#pragma unroll
            for (int q = 0; q < 4; q++) acc[mi][ni][q] = 0.0f;

    load_chunk(0, 0);
    load_chunk(1, 1);

    const int aRow  = wm + (lane & 15);
    const int bRow  = wn + (lane & 15);
    const int colHB = (lane >> 4) * 16;

    for (int c = 0; c < nc; c++) {
        if (c + 1 < nc) asm volatile("cp.async.wait_group 1;" ::: "memory");
        else            asm volatile("cp.async.wait_group 0;" ::: "memory");
        __syncthreads();
        if (c + 2 < nc) load_chunk(c + 2, (c + 2) % NSTAGE);

        const uint32_t sa = SM + (c % NSTAGE) * STG;
        const uint32_t sb = sa + A_STG;

#pragma unroll
        for (int ks = 0; ks < KC / 16; ks++) {
            uint32_t a[4][4], b[2][4];
#pragma unroll
            for (int mi = 0; mi < 4; mi++) {
                uint32_t addr = sa + sw128((uint32_t)((aRow + mi * 16) * 128 + ks * 32 + colHB));
                asm volatile("ldmatrix.sync.aligned.m8n8.x4.shared.b16 {%0,%1,%2,%3}, [%4];"
                             : "=r"(a[mi][0]), "=r"(a[mi][1]), "=r"(a[mi][2]), "=r"(a[mi][3])
                             : "r"(addr));
            }
#pragma unroll
            for (int nj = 0; nj < 2; nj++) {
                uint32_t addr = sb + sw128((uint32_t)((bRow + nj * 16) * 128 + ks * 32 + colHB));
                asm volatile("ldmatrix.sync.aligned.m8n8.x4.shared.b16 {%0,%1,%2,%3}, [%4];"
                             : "=r"(b[nj][0]), "=r"(b[nj][1]), "=r"(b[nj][2]), "=r"(b[nj][3])
                             : "r"(addr));
            }
#pragma unroll
            for (int mi = 0; mi < 4; mi++)
#pragma unroll
                for (int ni = 0; ni < 4; ni++) {
                    const int nj = ni >> 1, sl = ni & 1;
                    asm volatile(
                        "mma.sync.aligned.m16n8k16.row.col.f32.f16.f16.f32 "
                        "{%0,%1,%2,%3}, {%4,%5,%6,%7}, {%8,%9}, {%0,%1,%2,%3};"
                        : "+f"(acc[mi][ni][0]), "+f"(acc[mi][ni][1]),
                          "+f"(acc[mi][ni][2]), "+f"(acc[mi][ni][3])
                        : "r"(a[mi][0]), "r"(a[mi][1]), "r"(a[mi][2]), "r"(a[mi][3]),
                          "r"(b[nj][sl]), "r"(b[nj][sl + 2]));
                }
        }
    }

    const int r0 = m0 + wm + (lane >> 2);
    const int c0 = n0 + wn + (lane & 3) * 2;

    if (!is_attn) {
        // standard fp16 store
#pragma unroll
        for (int mi = 0; mi < 4; mi++) {
#pragma unroll
            for (int ni = 0; ni < 4; ni++) {
                int col = cbase + wn + (lane & 3) * 2 + ni * 8;
                uint32_t h0 = pack_half2(acc[mi][ni][0], acc[mi][ni][1]);
                uint32_t h1 = pack_half2(acc[mi][ni][2], acc[mi][ni][3]);
                *(uint32_t*)(C + (size_t)(r0 + mi * 16) * Ncols + col) = h0;
                *(uint32_t*)(C + (size_t)(r0 + mi * 16 + 8) * Ncols + col) = h1;
            }
        }
    } else {
        // attn partials: per-row {sum im*hx, sum im^2, sum im*bm} over this
        // warp's 32-col slice; quad-reduce then unique store.
        const int chunk = (n0 >> 5) + (wn >> 5);   // 0..31
#pragma unroll
        for (int mi = 0; mi < 4; mi++) {
#pragma unroll
            for (int h = 0; h < 2; h++) {
                int row = r0 + mi * 16 + h * 8;
                float dotp = 0.0f, n1 = 0.0f, ibm = 0.0f;
#pragma unroll
                for (int ni = 0; ni < 4; ni++) {
                    int col = c0 + ni * 8;
                    float v0 = acc[mi][ni][2 * h];
                    float v1 = acc[mi][ni][2 * h + 1];
                    __half2 hh = *(const __half2*)(g_axh + (size_t)row * K2 + 1024 + col);
                    float2 hf = __half22float2(hh);
                    float2 bv = *(const float2*)(bm + col);
                    dotp = fmaf(v0, hf.x, fmaf(v1, hf.y, dotp));
                    n1   = fmaf(v0, v0,   fmaf(v1, v1,   n1));
                    ibm  = fmaf(v0, bv.x, fmaf(v1, bv.y, ibm));
                }
                dotp += __shfl_xor_sync(0xffffffffu, dotp, 1);
                dotp += __shfl_xor_sync(0xffffffffu, dotp, 2);
                n1   += __shfl_xor_sync(0xffffffffu, n1, 1);
                n1   += __shfl_xor_sync(0xffffffffu, n1, 2);
                ibm  += __shfl_xor_sync(0xffffffffu, ibm, 1);
                ibm  += __shfl_xor_sync(0xffffffffu, ibm, 2);
                if ((lane & 3) == 0) {
                    g_part[(size_t)0 * B_DIM * 32 + (size_t)row * 32 + chunk] = dotp;
                    g_part[(size_t)1 * B_DIM * 32 + (size_t)row * 32 + chunk] = n1;
                    g_part[(size_t)2 * B_DIM * 32 + (size_t)row * 32 + chunk] = ibm;
                }
            }
        }
    }
}

// ---------------------------------------------------------------------------
// Merged prep (one launch):
//   seg 1: Wm transpose tiles      [0, WM_TILES)
//   seg 2: W transpose tiles       [WM_TILES, WM_TILES+W_TILES)
//   seg 3: hx convert + per-row sums  (1024 blocks, 8 rows each)
//   seg 4: x convert (grid-stride)    (1024 blocks)
// ---------------------------------------------------------------------------
#define WM_TILES ((H_DIM / 32) * (I_DIM / 32))               // 1024
#define W_TILES  ((K2 / 32) * (N4 / 32))                     // 8192
#define HX_BLKS  1024
#define X_BLKS   1024

__global__ __launch_bounds__(256)
void prep_all(const float* __restrict__ W, const float* __restrict__ Wm,
              const float* __restrict__ x, const float* __restrict__ hx,
              const float* __restrict__ bm)
{
    __shared__ float t[32][33];
    int bid = blockIdx.x;
    if (bid < WM_TILES + W_TILES) {
        const int tx = threadIdx.x & 31, ty = threadIdx.x >> 5;
        if (bid < WM_TILES) {
            int cx = bid & (H_DIM / 32 - 1), ry = bid / (H_DIM / 32);
            int r0 = ry * 32, c0 = cx * 32;
            for (int i = ty; i < 32; i += 8)
                t[i][tx] = Wm[(size_t)(r0 + i) * H_DIM + c0 + tx];
            __syncthreads();
            for (int j = ty; j < 32; j += 8)
                g_bt[(size_t)(c0 + j) * KDIM + r0 + tx] = __float2half_rn(t[tx][j]);
        } else {
            bid -= WM_TILES;
            int cx = bid & (N4 / 32 - 1), ry = bid / (N4 / 32);
            int r0 = ry * 32, c0 = cx * 32;
            for (int i = ty; i < 32; i += 8)
                t[i][tx] = W[(size_t)(r0 + i) * N4 + c0 + tx];
            __syncthreads();
            int base = (r0 < 1024) ? 1024 : 5120;
            int kloc = (r0 < 1024) ? r0 : (r0 - 1024);
            for (int j = ty; j < 32; j += 8)
                g_bt[(size_t)(base + c0 + j) * KDIM + kloc + tx] = __float2half_rn(t[tx][j]);
        }
    } else if (bid < WM_TILES + W_TILES + HX_BLKS) {
        // hx: row-coherent convert + per-row reductions
        int b2 = bid - (WM_TILES + W_TILES);
        const int warp = threadIdx.x >> 5;
        const int lane = threadIdx.x & 31;
        const int row = b2 * 8 + warp;
        float s2 = 0.0f, sbh = 0.0f;
#pragma unroll
        for (int i = 0; i < 8; i++) {
            int col = i * 128 + lane * 4;
            float4 v = *(const float4*)(hx + (size_t)row * 1024 + col);
            float4 bv = *(const float4*)(bm + col);
            uint2 o;
            o.x = pack_half2(v.x, v.y);
            o.y = pack_half2(v.z, v.w);
            *(uint2*)(g_axh + (size_t)row * K2 + 1024 + col) = o;
            s2  = fmaf(v.x, v.x, fmaf(v.y, v.y, fmaf(v.z, v.z, fmaf(v.w, v.w, s2))));
            sbh = fmaf(v.x, bv.x, fmaf(v.y, bv.y, fmaf(v.z, bv.z, fmaf(v.w, bv.w, sbh))));
        }
#pragma unroll
        for (int o = 16; o > 0; o >>= 1) {
            s2  += __shfl_xor_sync(0xffffffffu, s2, o);
            sbh += __shfl_xor_sync(0xffffffffu, sbh, o);
        }
        if (lane == 0) { g_hx2[row] = s2; g_hxbm[row] = sbh; }
        // one warp also computes ||bm||^2
        if (b2 == 0 && warp == 0) {
            float s = 0.0f;
#pragma unroll
            for (int i = 0; i < 8; i++) {
                int col = i * 128 + lane * 4;
                float4 bv = *(const float4*)(bm + col);
                s = fmaf(bv.x, bv.x, fmaf(bv.y, bv.y, fmaf(bv.z, bv.z, fmaf(bv.w, bv.w, s))));
            }
#pragma unroll
            for (int o = 16; o > 0; o >>= 1) s += __shfl_xor_sync(0xffffffffu, s, o);
            if (lane == 0) g_bm2[0] = s;
        }
    } else {
        // x convert (grid-stride over float4 chunks)
        int b3 = bid - (WM_TILES + W_TILES + HX_BLKS);
        const int Q1 = (B_DIM * I_DIM) / 4;
        for (int q = b3 * 256 + threadIdx.x; q < Q1; q += X_BLKS * 256) {
            int r = q >> 8, c4 = q & 255;
            float4 v = ((const float4*)x)[q];
            uint2 o;
            o.x = pack_half2(v.x, v.y);
            o.y = pack_half2(v.z, v.w);
            *(uint2*)(g_axh + (size_t)r * K2 + c4 * 4) = o;
        }
    }
}

// ---------------------------------------------------------------------------
__device__ __forceinline__ void block_reduce(float* vals, int n, float* sh, float* outp)
{
    const int lane = threadIdx.x & 31;
    const int warp = threadIdx.x >> 5;
    const int nw   = blockDim.x >> 5;
    for (int q = 0; q < n; q++) {
        float v = vals[q];
#pragma unroll
        for (int o = 16; o > 0; o >>= 1) v += __shfl_xor_sync(0xffffffffu, v, o);
        if (lane == 0) sh[warp * 8 + q] = v;
    }
    __syncthreads();
    if (warp < n) {
        float v = (lane < nw) ? sh[lane * 8 + warp] : 0.0f;
#pragma unroll
        for (int o = 16; o > 0; o >>= 1) v += __shfl_xor_sync(0xffffffffu, v, o);
        if (lane == 0) outp[warp] = v;
    }
    __syncthreads();
}

// ---------------------------------------------------------------------------
// Mega-epilogue v4: attn from precomputed partials (no c1/hx re-read),
// then gates+LN+cell+cosine. 256 thr/CTA, 4 elem/thread.
// ---------------------------------------------------------------------------
__global__ __launch_bounds__(256, 4)
void epilogue_kernel(const float* __restrict__ cx, const float* __restrict__ b,
                     const float* __restrict__ gammas, const float* __restrict__ betas,
                     float* __restrict__ out)
{
    __shared__ float sh[32 * 8];
    __shared__ float outp[8];
    __shared__ float shA[3];
    const int r = blockIdx.x;
    const int t = threadIdx.x;
    const int e = 4 * t;
    const int warp = t >> 5;
    const int lane = t & 31;

    // ---- phase A: s from partials ----
    if (warp < 3) {
        float v = g_part[((size_t)warp * B_DIM + r) * 32 + lane];
#pragma unroll
        for (int o = 16; o > 0; o >>= 1) v += __shfl_xor_sync(0xffffffffu, v, o);
        if (lane == 0) shA[warp] = v;
    }
    __syncthreads();
    float dot = shA[0] + g_hxbm[r];
    float n1  = shA[1] + 2.0f * shA[2] + g_bm2[0];
    float na0 = fmaxf(sqrtf(n1), 1e-6f);
    float nb0 = fmaxf(sqrtf(g_hx2[r]), 1e-6f);
    float s = 1.0f + sigmoidf_(dot / (na0 * nb0));

    const __half* c1row = g_c1p + (size_t)r * N4;
    const __half* c2row = g_c2  + (size_t)r * N4;

    // ---- phase B: gates = s*P + Q + b;  row sums & sumsq ----
    float v[4][4];
    float vals[8];
#pragma unroll
    for (int q = 0; q < 8; q++) vals[q] = 0.0f;
#pragma unroll
    for (int q = 0; q < 4; q++) {
        uint2 pv = *(const uint2*)(c1row + q * 1024 + e);
        uint2 qv = *(const uint2*)(c2row + q * 1024 + e);
        float2 p01 = __half22float2(*reinterpret_cast<__half2*>(&pv.x));
        float2 p23 = __half22float2(*reinterpret_cast<__half2*>(&pv.y));
        float2 q01 = __half22float2(*reinterpret_cast<__half2*>(&qv.x));
        float2 q23 = __half22float2(*reinterpret_cast<__half2*>(&qv.y));
        float4 b4 = *(const float4*)(b + q * 1024 + e);
        v[q][0] = fmaf(s, p01.x, q01.x) + b4.x;
        v[q][1] = fmaf(s, p01.y, q01.y) + b4.y;
        v[q][2] = fmaf(s, p23.x, q23.x) + b4.z;
        v[q][3] = fmaf(s, p23.y, q23.y) + b4.w;
#pragma unroll
        for (int k = 0; k < 4; k++) {
            vals[q]     += v[q][k];
            vals[q + 4]  = fmaf(v[q][k], v[q][k], vals[q + 4]);
        }
    }
    block_reduce(vals, 8, sh, outp);

    // ---- fold LN affine into v in place ----
    const float invH = 1.0f / 1024.0f;
#pragma unroll
    for (int q = 0; q < 4; q++) {
        float mu = outp[q] * invH;
        float var = outp[q + 4] * invH - mu * mu;
        float rs = rsqrtf(var + 1e-5f);
        float4 ga = *(const float4*)(gammas + q * 1024 + e);
        float4 be = *(const float4*)(betas  + q * 1024 + e);
        v[q][0] = (v[q][0] - mu) * rs * ga.x + be.x;
        v[q][1] = (v[q][1] - mu) * rs * ga.y + be.y;
        v[q][2] = (v[q][2] - mu) * rs * ga.z + be.z;
        v[q][3] = (v[q][3] - mu) * rs * ga.w + be.w;
    }

    // ---- phase C: activations + cell update + cosine gate ----
    float4 cx4 = *(const float4*)(cx + (size_t)r * 1024 + e);
    const float cxe[4] = {cx4.x, cx4.y, cx4.z, cx4.w};

    float hxn[4], cxn[4];
    float d2 = 0, h2 = 0, c2 = 0;
#pragma unroll
    for (int k = 0; k < 4; k++) {
        float i_g = sigmoidf_(v[0][k]);
        float f_g = sigmoidf_(v[1][k]);
        float g_g = tanhf_(v[2][k]);
        float o_g = sigmoidf_(v[3][k]);
        float cn = fmaf(f_g, cxe[k], i_g * g_g);
        float hn = o_g * tanhf_(cn);
        cxn[k] = cn; hxn[k] = hn;
        d2 = fmaf(hn, cn, d2);
        h2 = fmaf(hn, hn, h2);
        c2 = fmaf(cn, cn, c2);
    }
    float vals2[3] = {d2, h2, c2};
    block_reduce(vals2, 3, sh, outp);

    float na = fmaxf(sqrtf(outp[1]), 1e-6f);
    float nb = fmaxf(sqrtf(outp[2]), 1e-6f);
    float gc = sigmoidf_((outp[0] / (na * nb) + 1.0f) * 0.5f);
    float gs = 1.0f + gc;

    float4 o1 = make_float4(hxn[0] * gs, hxn[1] * gs, hxn[2] * gs, hxn[3] * gs);
    float4 o2 = make_float4(cxn[0], cxn[1], cxn[2], cxn[3]);
    *(float4*)(out + (size_t)r * 1024 + e) = o1;
    *(float4*)(out + (size_t)B_DIM * 1024 + (size_t)r * 1024 + e) = o2;
}

// ---------------------------------------------------------------------------
extern "C" void kernel_launch(void* const* d_in, const int* in_sizes, int n_in,
                              void* d_out, int out_size)
{
    const float* x      = (const float*)d_in[0];
    const float* hx     = (const float*)d_in[1];
    const float* cx     = (const float*)d_in[2];
    const float* W      = (const float*)d_in[3];   // [2048, 4096]
    const float* b      = (const float*)d_in[4];   // [4096]
    const float* Wm     = (const float*)d_in[5];   // [1024, 1024]
    const float* bm     = (const float*)d_in[6];   // [1024]
    const float* gammas = (const float*)d_in[7];
    const float* betas  = (const float*)d_in[8];
    float* out = (float*)d_out;

    cudaFuncSetAttribute(hgemm_dual, cudaFuncAttributeMaxDynamicSharedMemorySize,
                         GEMM_SMEM);

    // (1) merged prep: transposes + activation rounding + attn row stats
    prep_all<<<WM_TILES + W_TILES + HX_BLKS + X_BLKS, 256>>>(W, Wm, x, hx, bm);

    // (2) fused dual GEMM + attn partials
    hgemm_dual<<<GRID_A + GRID_B, 256, GEMM_SMEM>>>(bm);

    // (3) mega-epilogue v4
    epilogue_kernel<<<B_DIM, 256>>>(cx, b, gammas, betas, out);
}